// round 16
// baseline (speedup 1.0000x reference)
#include <cuda_runtime.h>

#define N_POINTS 32768
#define N_PRIMS  2048
#define SEG_P    (N_PRIMS / 8)
#define TILE     256
#define NPAIR    (TILE / 2)
#define BLOCK    256
#define SGRID    74
#define NWARP_PT (N_POINTS / 64)
#define PBINS    4096
#define CUT      18.0f

typedef unsigned long long ull;

__device__ __forceinline__ float fsqrt_ap(float x) { float r; asm("sqrt.approx.f32 %0, %1;" : "=f"(r) : "f"(x)); return r; }
__device__ __forceinline__ float fex2_ap (float x) { float r; asm("ex2.approx.f32 %0, %1;"  : "=f"(r) : "f"(x)); return r; }
__device__ __forceinline__ float fcos_ap (float x) { float r; asm("cos.approx.f32 %0, %1;"  : "=f"(r) : "f"(x)); return r; }
__device__ __forceinline__ float fsin_ap (float x) { float r; asm("sin.approx.f32 %0, %1;"  : "=f"(r) : "f"(x)); return r; }
__device__ __forceinline__ float flg2_ap (float x) { float r; asm("lg2.approx.f32 %0, %1;"  : "=f"(r) : "f"(x)); return r; }

__device__ __forceinline__ ull pk2(float a, float b) { ull r; asm("mov.b64 %0, {%1, %2};" : "=l"(r) : "f"(a), "f"(b)); return r; }
__device__ __forceinline__ void upk2(float& a, float& b, ull v) { asm("mov.b64 {%0, %1}, %2;" : "=f"(a), "=f"(b) : "l"(v)); }
__device__ __forceinline__ ull add2(ull a, ull b) { ull r; asm("add.rn.f32x2 %0, %1, %2;" : "=l"(r) : "l"(a), "l"(b)); return r; }
__device__ __forceinline__ ull mul2(ull a, ull b) { ull r; asm("mul.rn.f32x2 %0, %1, %2;" : "=l"(r) : "l"(a), "l"(b)); return r; }
__device__ __forceinline__ ull fma2(ull a, ull b, ull c) { ull r; asm("fma.rn.f32x2 %0, %1, %2, %3;" : "=l"(r) : "l"(a), "l"(b), "l"(c)); return r; }
__device__ __forceinline__ ull abs2(ull v) { return v & 0x7FFFFFFF7FFFFFFFULL; }

// ---- device scratch ----
__device__ int   g_neg6, g_neg2;
__device__ int   g_histP[PBINS];
__device__ float g_sx[N_POINTS], g_sy[N_POINTS], g_sz[N_POINTS];
__device__ int   g_sidx[N_POINTS];
__device__ float g_ppx[N_PRIMS], g_ppy[N_PRIMS], g_ppz[N_PRIMS];
__device__ float g_civx[N_PRIMS], g_civy[N_PRIMS], g_civz[N_PRIMS];
__device__ float g_pla[N_PRIMS], g_pph[N_PRIMS];

__device__ __forceinline__ int spread3(int v) {
    return (v & 1) | ((v & 2) << 2) | ((v & 4) << 4) | ((v & 8) << 6);
}
__device__ __forceinline__ int pt_bin(float x, float y, float z) {
    int ix = min(15, max(0, (int)floorf(x + 8.0f)));
    int iy = min(15, max(0, (int)floorf(y + 8.0f)));
    int iz = min(15, max(0, (int)floorf(z + 8.0f)));
    return (spread3(ix) << 2) | (spread3(iy) << 1) | spread3(iz);
}

// K1: zero output; block 0 classifies ambiguous inputs
__global__ __launch_bounds__(256) void k_zero_classify(
    float* __restrict__ out, int n_out,
    const float* __restrict__ c6a, const float* __restrict__ c2a)
{
    if (blockIdx.x == 0) {
        const int tid = threadIdx.x;
        const int n6 = __syncthreads_count(c6a[tid * 24] < 0.0f);
        const int n2 = __syncthreads_count(c2a[tid * 8] < 0.0f);
        if (tid == 0) { g_neg6 = n6; g_neg2 = n2; }
    }
    const int i = blockIdx.x * 256 + threadIdx.x;
    if (i < n_out) out[i] = 0.0f;
}

// K2: fused histogram + exclusive scan (single block, smem hist)
__global__ __launch_bounds__(1024) void k_histscan(const float* __restrict__ qp) {
    __shared__ int h[PBINS];     // 16 KB
    __shared__ int sm[1024];
    const int t = threadIdx.x;
    #pragma unroll
    for (int k = 0; k < 4; ++k) h[t + k * 1024] = 0;
    __syncthreads();
    for (int i = t; i < N_POINTS; i += 1024)
        atomicAdd(&h[pt_bin(qp[3*i], qp[3*i+1], qp[3*i+2])], 1);
    __syncthreads();
    int loc[4]; int sum = 0;
    #pragma unroll
    for (int k = 0; k < 4; ++k) { loc[k] = h[t*4 + k]; sum += loc[k]; }
    sm[t] = sum; __syncthreads();
    for (int off = 1; off < 1024; off <<= 1) {
        int v = (t >= off) ? sm[t - off] : 0;
        __syncthreads(); sm[t] += v; __syncthreads();
    }
    int run = sm[t] - sum;
    #pragma unroll
    for (int k = 0; k < 4; ++k) { g_histP[t*4 + k] = run; run += loc[k]; }
}

// K3: scatter points (sorted) + derive prim params
__global__ __launch_bounds__(256) void k_scatter(
    const float* __restrict__ qp,
    const float* __restrict__ c6a, const float* __restrict__ c6b,
    const float* __restrict__ c2a, const float* __restrict__ c2b)
{
    const float NEG_HALF_LOG2E = -0.7213475204444817f;
    const int i = blockIdx.x * 256 + threadIdx.x;
    if (i < N_POINTS) {
        const float x = qp[3*i], y = qp[3*i+1], z = qp[3*i+2];
        const int slot = atomicAdd(&g_histP[pt_bin(x, y, z)], 1);
        g_sx[slot] = x; g_sy[slot] = y; g_sz[slot] = z; g_sidx[slot] = i;
    }
    if (i < N_PRIMS) {
        const float* pos = g_neg6 ? c6a : c6b;
        const float* scl = g_neg6 ? c6b : c6a;
        const float* phs = g_neg2 ? c2a : c2b;
        const float* amp = g_neg2 ? c2b : c2a;
        const float sx = scl[3*i], sy = scl[3*i+1], sz = scl[3*i+2];
        g_ppx[i] = pos[3*i]; g_ppy[i] = pos[3*i+1]; g_ppz[i] = pos[3*i+2];
        g_civx[i] = NEG_HALF_LOG2E * __frcp_rn(sx * sx);
        g_civy[i] = NEG_HALF_LOG2E * __frcp_rn(sy * sy);
        g_civz[i] = NEG_HALF_LOG2E * __frcp_rn(sz * sz);
        g_pla[i]  = flg2_ap(amp[i]);
        g_pph[i]  = phs[i];
    }
}

// K4: main — per-dim bounding-box cull, warp-uniform continue
template <bool NEED_IM>
__global__ __launch_bounds__(BLOCK, 3) void complex_field_kernel(
    const void* __restrict__ freq_ptr, float* __restrict__ out)
{
    const int tid  = threadIdx.x;
    const int wid  = tid >> 5;
    const int lane = tid & 31;

    float f = 2400000000.0f;
    if (freq_ptr) {
        const int   iv = *(const int*)freq_ptr;
        const float fv = __int_as_float(iv);
        if (fv > 1.0e5f && fv < 1.0e12f)  f = fv;
        else if (iv > 0)                  f = (float)iv;
    }
    const float kw = 6.2831855f * f / 299792458.0f;

    const int seg   = blockIdx.x / SGRID;
    const int pbase = seg * SEG_P;
    const int wtask = (blockIdx.x % SGRID) + SGRID * wid;
    const bool active = (wtask < NWARP_PT);
    const int n0 = wtask * 64 + lane;
    const int n1 = n0 + 32;

    __shared__ ulonglong2 s_P[NPAIR];   // {(-pxa,-pxb), (-pya,-pyb)}
    __shared__ ulonglong2 s_Q[NPAIR];   // {(-pza,-pzb), (pha, phb)}
    __shared__ ulonglong2 s_R[NPAIR];   // {(civxa,civxb), (civya,civyb)}
    __shared__ ulonglong2 s_S[NPAIR];   // {(civza,civzb), (laa, lab)}
    {
        const int j = pbase + tid;
        const int q = tid >> 1, l = tid & 1;
        float* Pf = (float*)s_P; float* Qf = (float*)s_Q;
        float* Rf = (float*)s_R; float* Sf = (float*)s_S;
        Pf[q*4 + 0 + l] = -g_ppx[j];
        Pf[q*4 + 2 + l] = -g_ppy[j];
        Qf[q*4 + 0 + l] = -g_ppz[j];
        Qf[q*4 + 2 + l] =  g_pph[j];
        Rf[q*4 + 0 + l] =  g_civx[j];
        Rf[q*4 + 2 + l] =  g_civy[j];
        Sf[q*4 + 0 + l] =  g_civz[j];
        Sf[q*4 + 2 + l] =  g_pla[j];
    }
    __syncthreads();

    if (!active) return;

    const float x0 = g_sx[n0], y0 = g_sy[n0], z0 = g_sz[n0];
    const float x1 = g_sx[n1], y1 = g_sy[n1], z1 = g_sz[n1];
    const int idx0 = g_sidx[n0], idx1 = g_sidx[n1];

    // per-dim bounding BOX of the warp's 64 Morton-adjacent points
    float mnx = fminf(x0, x1), mxx = fmaxf(x0, x1);
    float mny = fminf(y0, y1), mxy = fmaxf(y0, y1);
    float mnz = fminf(z0, z1), mxz = fmaxf(z0, z1);
    #pragma unroll
    for (int o = 16; o > 0; o >>= 1) {
        mnx = fminf(mnx, __shfl_xor_sync(0xffffffffu, mnx, o));
        mxx = fmaxf(mxx, __shfl_xor_sync(0xffffffffu, mxx, o));
        mny = fminf(mny, __shfl_xor_sync(0xffffffffu, mny, o));
        mxy = fmaxf(mxy, __shfl_xor_sync(0xffffffffu, mxy, o));
        mnz = fminf(mnz, __shfl_xor_sync(0xffffffffu, mnz, o));
        mxz = fmaxf(mxz, __shfl_xor_sync(0xffffffffu, mxz, o));
    }
    const float cx = 0.5f * (mnx + mxx), hx = 0.5f * (mxx - mnx);
    const float cy = 0.5f * (mny + mxy), hy = 0.5f * (mxy - mny);
    const float cz = 0.5f * (mnz + mxz), hz = 0.5f * (mxz - mnz);

    const ull cx2 = pk2(cx, cx), cy2 = pk2(cy, cy), cz2 = pk2(cz, cz);
    const ull nhx2 = pk2(-hx, -hx), nhy2 = pk2(-hy, -hy), nhz2 = pk2(-hz, -hz);
    const ull QUARTER2 = pk2(0.25f, 0.25f);

    const ull x00 = pk2(x0, x0), y00 = pk2(y0, y0), z00 = pk2(z0, z0);
    const ull x11 = pk2(x1, x1), y11 = pk2(y1, y1), z11 = pk2(z1, z1);
    ull re0 = 0ull, re1 = 0ull, im0 = 0ull, im1 = 0ull;

    #pragma unroll 2
    for (int i = 0; i < NPAIR; ++i) {
        const ulonglong2 P = s_P[i];
        const ulonglong2 Q = s_Q[i];
        const ulonglong2 R = s_R[i];
        const ulonglong2 S = s_S[i];

        // box lower bound on maha: e_ub = sum civ_i*relu(|c_i-p_i|-h_i)^2 + la
        {
            ull t, u1, u2, u3;
            t = add2(abs2(add2(cx2, P.x)), nhx2); u1 = add2(t, abs2(t));  // 2*relu
            t = add2(abs2(add2(cy2, P.y)), nhy2); u2 = add2(t, abs2(t));
            t = add2(abs2(add2(cz2, Q.x)), nhz2); u3 = add2(t, abs2(t));
            ull e4 = mul2(u3, mul2(u3, S.x));
            e4 = fma2(u2, mul2(u2, R.y), e4);
            e4 = fma2(u1, mul2(u1, R.x), e4);
            const ull eub = fma2(QUARTER2, e4, S.y);
            float eua, eubv; upk2(eua, eubv, eub);
            if (eua <= -CUT && eubv <= -CUT) continue;   // warp-uniform skip
        }

        float phpa, phpb; upk2(phpa, phpb, Q.y);
        // ---- point 0 ----
        {
            const ull dx = add2(x00, P.x);
            const ull dy = add2(y00, P.y);
            const ull dz = add2(z00, Q.x);
            const ull dx2 = mul2(dx, dx);
            const ull dy2 = mul2(dy, dy);
            const ull dz2 = mul2(dz, dz);
            const ull d2  = add2(add2(dx2, dy2), dz2);
            const ull e   = fma2(dx2, R.x, fma2(dy2, R.y, fma2(dz2, S.x, S.y)));
            float d2a, d2b; upk2(d2a, d2b, d2);
            float ea,  eb;  upk2(ea,  eb,  e);
            const float ra = fsqrt_ap(d2a), rb = fsqrt_ap(d2b);
            const float wa = fex2_ap(ea),   wb = fex2_ap(eb);
            const float pa = fmaf(kw, ra, phpa), pb = fmaf(kw, rb, phpb);
            re0 = fma2(pk2(wa, wb), pk2(fcos_ap(pa), fcos_ap(pb)), re0);
            if (NEED_IM)
                im0 = fma2(pk2(wa, wb), pk2(fsin_ap(pa), fsin_ap(pb)), im0);
        }
        // ---- point 1 ----
        {
            const ull dx = add2(x11, P.x);
            const ull dy = add2(y11, P.y);
            const ull dz = add2(z11, Q.x);
            const ull dx2 = mul2(dx, dx);
            const ull dy2 = mul2(dy, dy);
            const ull dz2 = mul2(dz, dz);
            const ull d2  = add2(add2(dx2, dy2), dz2);
            const ull e   = fma2(dx2, R.x, fma2(dy2, R.y, fma2(dz2, S.x, S.y)));
            float d2a, d2b; upk2(d2a, d2b, d2);
            float ea,  eb;  upk2(ea,  eb,  e);
            const float ra = fsqrt_ap(d2a), rb = fsqrt_ap(d2b);
            const float wa = fex2_ap(ea),   wb = fex2_ap(eb);
            const float pa = fmaf(kw, ra, phpa), pb = fmaf(kw, rb, phpb);
            re1 = fma2(pk2(wa, wb), pk2(fcos_ap(pa), fcos_ap(pb)), re1);
            if (NEED_IM)
                im1 = fma2(pk2(wa, wb), pk2(fsin_ap(pa), fsin_ap(pb)), im1);
        }
    }

    float a, b;
    upk2(a, b, re0); atomicAdd(&out[idx0], a + b);
    upk2(a, b, re1); atomicAdd(&out[idx1], a + b);
    if (NEED_IM) {
        upk2(a, b, im0); atomicAdd(&out[N_POINTS + idx0], a + b);
        upk2(a, b, im1); atomicAdd(&out[N_POINTS + idx1], a + b);
    }
}

extern "C" void kernel_launch(void* const* d_in, const int* in_sizes, int n_in,
                              void* d_out, int out_size) {
    const float* qp = nullptr;
    const float* p6[2] = {nullptr, nullptr};
    const float* p2[2] = {nullptr, nullptr};
    const void*  freq = nullptr;
    int n6 = 0, n2 = 0;

    for (int i = 0; i < n_in; ++i) {
        const int sz = in_sizes[i];
        if      (sz == 3 * N_POINTS)           qp = (const float*)d_in[i];
        else if (sz == 3 * N_PRIMS && n6 < 2)  p6[n6++] = (const float*)d_in[i];
        else if (sz == N_PRIMS && n2 < 2)      p2[n2++] = (const float*)d_in[i];
        else if (sz == 1)                      freq = d_in[i];
    }

    float* out = (float*)d_out;
    const bool need_im = (out_size >= 2 * N_POINTS);
    const int  n_out   = need_im ? 2 * N_POINTS : N_POINTS;

    k_zero_classify<<<(n_out + 255) / 256, 256>>>(out, n_out, p6[0], p2[0]);
    k_histscan<<<1, 1024>>>(qp);
    k_scatter<<<N_POINTS / 256, 256>>>(qp, p6[0], p6[1], p2[0], p2[1]);

    if (need_im) complex_field_kernel<true ><<<8 * SGRID, BLOCK>>>(freq, out);
    else         complex_field_kernel<false><<<8 * SGRID, BLOCK>>>(freq, out);
}

// round 17
// speedup vs baseline: 1.5327x; 1.5327x over previous
#include <cuda_runtime.h>

#define N_POINTS 32768
#define N_PRIMS  2048
#define SEG_P    (N_PRIMS / 8)
#define TILE     256
#define NPAIR    (TILE / 2)
#define BLOCK    256
#define SGRID    74
#define NWARP_PT (N_POINTS / 64)

typedef unsigned long long ull;

__device__ __forceinline__ float fsqrt_ap(float x) { float r; asm("sqrt.approx.f32 %0, %1;" : "=f"(r) : "f"(x)); return r; }
__device__ __forceinline__ float fex2_ap (float x) { float r; asm("ex2.approx.f32 %0, %1;"  : "=f"(r) : "f"(x)); return r; }
__device__ __forceinline__ float fcos_ap (float x) { float r; asm("cos.approx.f32 %0, %1;"  : "=f"(r) : "f"(x)); return r; }
__device__ __forceinline__ float fsin_ap (float x) { float r; asm("sin.approx.f32 %0, %1;"  : "=f"(r) : "f"(x)); return r; }
__device__ __forceinline__ float flg2_ap (float x) { float r; asm("lg2.approx.f32 %0, %1;"  : "=f"(r) : "f"(x)); return r; }

// ---- pack/unpack via bitcast (ptxas-coalescible; NOT opaque inline asm) ----
union f2u { ull u; float2 f; };
__device__ __forceinline__ ull pk2(float a, float b) {
    f2u v; v.f.x = a; v.f.y = b; return v.u;
}
__device__ __forceinline__ void upk2(float& a, float& b, ull v) {
    f2u w; w.u = v; a = w.f.x; b = w.f.y;
}
// ---- packed f32x2 arithmetic (Blackwell; PTX-only, stays as asm) ----
__device__ __forceinline__ ull add2(ull a, ull b) { ull r; asm("add.rn.f32x2 %0, %1, %2;" : "=l"(r) : "l"(a), "l"(b)); return r; }
__device__ __forceinline__ ull mul2(ull a, ull b) { ull r; asm("mul.rn.f32x2 %0, %1, %2;" : "=l"(r) : "l"(a), "l"(b)); return r; }
__device__ __forceinline__ ull fma2(ull a, ull b, ull c) { ull r; asm("fma.rn.f32x2 %0, %1, %2, %3;" : "=l"(r) : "l"(a), "l"(b), "l"(c)); return r; }

__global__ __launch_bounds__(256) void zero_kernel(float* __restrict__ out, int n) {
    const int i = blockIdx.x * 256 + threadIdx.x;
    if (i < n) out[i] = 0.0f;
}

template <bool NEED_IM>
__global__ __launch_bounds__(BLOCK, 4) void complex_field_kernel(
    const float* __restrict__ qp,
    const float* __restrict__ c6a,
    const float* __restrict__ c6b,
    const float* __restrict__ c2a,
    const float* __restrict__ c2b,
    const void*  __restrict__ freq_ptr,
    float* __restrict__ out)
{
    const int tid  = threadIdx.x;
    const int wid  = tid >> 5;
    const int lane = tid & 31;

    // ---- input disambiguation by sign statistics ----
    const int neg6 = __syncthreads_count(c6a[tid * 24] < 0.0f);
    const float* pos = neg6 ? c6a : c6b;
    const float* scl = neg6 ? c6b : c6a;
    const int neg2 = __syncthreads_count(c2a[tid * 8] < 0.0f);
    const float* phs = neg2 ? c2a : c2b;
    const float* amp = neg2 ? c2b : c2a;

    // ---- wavenumber ----
    float f = 2400000000.0f;
    if (freq_ptr) {
        const int   iv = *(const int*)freq_ptr;
        const float fv = __int_as_float(iv);
        if (fv > 1.0e5f && fv < 1.0e12f)  f = fv;
        else if (iv > 0)                  f = (float)iv;
    }
    const float kw = 6.2831855f * f / 299792458.0f;
    const float NEG_HALF_LOG2E = -0.7213475204444817f;

    const int seg   = blockIdx.x / SGRID;
    const int pbase = seg * SEG_P;
    const int wtask = (blockIdx.x % SGRID) + SGRID * wid;
    const bool active = (wtask < NWARP_PT);
    const int n0 = wtask * 64 + lane;
    const int n1 = n0 + 32;

    float x0=0.f, y0=0.f, z0=0.f, x1=0.f, y1=0.f, z1=0.f;
    if (active) {
        x0 = qp[3*n0+0]; y0 = qp[3*n0+1]; z0 = qp[3*n0+2];
        x1 = qp[3*n1+0]; y1 = qp[3*n1+1]; z1 = qp[3*n1+2];
    }
    const ull x00 = pk2(x0, x0), y00 = pk2(y0, y0), z00 = pk2(z0, z0);
    const ull x11 = pk2(x1, x1), y11 = pk2(y1, y1), z11 = pk2(z1, z1);

    // prim-PAIR packed shared tiles (lane = prim a / prim b)
    __shared__ ulonglong2 s_P[NPAIR];   // {(-pxa,-pxb), (-pya,-pyb)}
    __shared__ ulonglong2 s_Q[NPAIR];   // {(-pza,-pzb), (pha, phb)}
    __shared__ ulonglong2 s_R[NPAIR];   // {(civxa,civxb), (civya,civyb)}  c=-0.5*log2 e
    __shared__ ulonglong2 s_S[NPAIR];   // {(civza,civzb), (laa, lab)}

    {
        const int j = pbase + tid;
        const int q = tid >> 1, l = tid & 1;
        float* Pf = (float*)s_P; float* Qf = (float*)s_Q;
        float* Rf = (float*)s_R; float* Sf = (float*)s_S;
        const float sx = scl[3*j+0], sy = scl[3*j+1], sz = scl[3*j+2];
        Pf[q*4 + 0 + l] = -pos[3*j+0];
        Pf[q*4 + 2 + l] = -pos[3*j+1];
        Qf[q*4 + 0 + l] = -pos[3*j+2];
        Qf[q*4 + 2 + l] =  phs[j];
        Rf[q*4 + 0 + l] = NEG_HALF_LOG2E * __frcp_rn(sx * sx);
        Rf[q*4 + 2 + l] = NEG_HALF_LOG2E * __frcp_rn(sy * sy);
        Sf[q*4 + 0 + l] = NEG_HALF_LOG2E * __frcp_rn(sz * sz);
        Sf[q*4 + 2 + l] = flg2_ap(amp[j]);   // amp=0 -> -inf -> ex2 -> 0
    }
    __syncthreads();

    ull re0 = 0ull, re1 = 0ull, im0 = 0ull, im1 = 0ull;

    if (active) {
        #pragma unroll 4
        for (int i = 0; i < NPAIR; ++i) {
            const ulonglong2 P = s_P[i];
            const ulonglong2 Q = s_Q[i];
            const ulonglong2 R = s_R[i];
            const ulonglong2 S = s_S[i];
            float phpa, phpb; upk2(phpa, phpb, Q.y);   // shared by both points

            // ---- point 0 vs prim pair ----
            {
                const ull dx = add2(x00, P.x);
                const ull dy = add2(y00, P.y);
                const ull dz = add2(z00, Q.x);
                const ull dx2 = mul2(dx, dx);
                const ull dy2 = mul2(dy, dy);
                const ull dz2 = mul2(dz, dz);
                const ull d2  = add2(add2(dx2, dy2), dz2);
                const ull e   = fma2(dx2, R.x, fma2(dy2, R.y, fma2(dz2, S.x, S.y)));
                float d2a, d2b; upk2(d2a, d2b, d2);
                float ea,  eb;  upk2(ea,  eb,  e);
                const float ra = fsqrt_ap(d2a), rb = fsqrt_ap(d2b);
                const float wa = fex2_ap(ea),   wb = fex2_ap(eb);
                const float pa = fmaf(kw, ra, phpa), pb = fmaf(kw, rb, phpb);
                re0 = fma2(pk2(wa, wb), pk2(fcos_ap(pa), fcos_ap(pb)), re0);
                if (NEED_IM)
                    im0 = fma2(pk2(wa, wb), pk2(fsin_ap(pa), fsin_ap(pb)), im0);
            }
            // ---- point 1 vs prim pair ----
            {
                const ull dx = add2(x11, P.x);
                const ull dy = add2(y11, P.y);
                const ull dz = add2(z11, Q.x);
                const ull dx2 = mul2(dx, dx);
                const ull dy2 = mul2(dy, dy);
                const ull dz2 = mul2(dz, dz);
                const ull d2  = add2(add2(dx2, dy2), dz2);
                const ull e   = fma2(dx2, R.x, fma2(dy2, R.y, fma2(dz2, S.x, S.y)));
                float d2a, d2b; upk2(d2a, d2b, d2);
                float ea,  eb;  upk2(ea,  eb,  e);
                const float ra = fsqrt_ap(d2a), rb = fsqrt_ap(d2b);
                const float wa = fex2_ap(ea),   wb = fex2_ap(eb);
                const float pa = fmaf(kw, ra, phpa), pb = fmaf(kw, rb, phpb);
                re1 = fma2(pk2(wa, wb), pk2(fcos_ap(pa), fcos_ap(pb)), re1);
                if (NEED_IM)
                    im1 = fma2(pk2(wa, wb), pk2(fsin_ap(pa), fsin_ap(pb)), im1);
            }
        }

        float a, b;
        upk2(a, b, re0); atomicAdd(&out[n0], a + b);
        upk2(a, b, re1); atomicAdd(&out[n1], a + b);
        if (NEED_IM) {
            upk2(a, b, im0); atomicAdd(&out[N_POINTS + n0], a + b);
            upk2(a, b, im1); atomicAdd(&out[N_POINTS + n1], a + b);
        }
    }
}

extern "C" void kernel_launch(void* const* d_in, const int* in_sizes, int n_in,
                              void* d_out, int out_size) {
    const float* qp = nullptr;
    const float* p6[2] = {nullptr, nullptr};
    const float* p2[2] = {nullptr, nullptr};
    const void*  freq = nullptr;
    int n6 = 0, n2 = 0;

    for (int i = 0; i < n_in; ++i) {
        const int sz = in_sizes[i];
        if      (sz == 3 * N_POINTS)           qp = (const float*)d_in[i];
        else if (sz == 3 * N_PRIMS && n6 < 2)  p6[n6++] = (const float*)d_in[i];
        else if (sz == N_PRIMS && n2 < 2)      p2[n2++] = (const float*)d_in[i];
        else if (sz == 1)                      freq = d_in[i];
    }

    float* out = (float*)d_out;
    const bool need_im = (out_size >= 2 * N_POINTS);
    const int  n_out   = need_im ? 2 * N_POINTS : N_POINTS;

    zero_kernel<<<(n_out + 255) / 256, 256>>>(out, n_out);

    if (need_im) {
        complex_field_kernel<true><<<8 * SGRID, BLOCK>>>(
            qp, p6[0], p6[1], p2[0], p2[1], freq, out);
    } else {
        complex_field_kernel<false><<<8 * SGRID, BLOCK>>>(
            qp, p6[0], p6[1], p2[0], p2[1], freq, out);
    }
}